// round 2
// baseline (speedup 1.0000x reference)
#include <cuda_runtime.h>

// Tile pitches (floats). 132*4=528 bytes: 16B aligned rows, bank step 4*132%32=16
// for row-group strided loads -> at most 2-way conflicts on A loads.
#define PITCH 132

// smem layout (floats):
//   s_x    : 128 rows x PITCH   ( [h (d 0..63)] [t (d 64..127)] per (k,f) row, row = k*4+f )
//   s_w1t  : 64 cols x PITCH    ( W1 transposed: s_w1t[col*PITCH + kk] = W1[kk*64+col] )
//   s_b1   : 64
//   s_w2   : 64
//   s_logit: 128
//   s_w    : 128
//   s_idx  : 64 ints (h idx 0..31, t idx 32..63)
#define SMEM_FLOATS (128*PITCH + 64*PITCH + 64 + 64 + 128 + 128 + 64)

__global__ __launch_bounds__(256, 2)
void kgat_fused_kernel(const float* __restrict__ node_emb,
                       const float* __restrict__ W1,
                       const float* __restrict__ b1,
                       const float* __restrict__ W2,
                       const float* __restrict__ b2,
                       const int*   __restrict__ users,
                       const int*   __restrict__ items,
                       const int*   __restrict__ users_triple,
                       const int*   __restrict__ items_triple,
                       float*       __restrict__ out)
{
    extern __shared__ float smem[];
    float* s_x     = smem;                    // 128*PITCH
    float* s_w1t   = s_x + 128 * PITCH;       // 64*PITCH
    float* s_b1    = s_w1t + 64 * PITCH;      // 64
    float* s_w2    = s_b1 + 64;               // 64
    float* s_logit = s_w2 + 64;               // 128
    float* s_w     = s_logit + 128;           // 128
    int*   s_idx   = (int*)(s_w + 128);       // 64

    const int bx    = blockIdx.x;
    const int tower = bx >> 11;        // 2048 blocks per tower
    const int b     = (bx >> 1) & 1023;
    const int layer = bx & 1;
    const int tid   = threadIdx.x;

    const int* triple   = tower ? items_triple : users_triple;
    const int* oidx_arr = tower ? items : users;

    // ---- Phase 0: indices + small params ----
    if (tid < 64) {
        int which = tid >> 5;          // 0 = h (c=0), 1 = t (c=2)
        int k     = tid & 31;
        int c     = which ? 2 : 0;
        // triple shape (B, 3, 2, 32): [b][c][layer][k]
        s_idx[tid] = triple[((b * 3 + c) * 2 + layer) * 32 + k];
        s_b1[tid] = b1[tid];
        s_w2[tid] = W2[tid];
    }
    __syncthreads();

    // ---- Origin copy (only layer-0 blocks own slot 0) ----
    if (layer == 0) {
        int oidx = oidx_arr[b];
        const float4* src = (const float4*)node_emb + (size_t)oidx * 64;
        float4* dst = (float4*)out + ((size_t)tower * 3 * 1024 + b) * 64;
        for (int i = tid; i < 64; i += 256) dst[i] = src[i];
    }

    // ---- Phase 1: gather h,t rows into s_x; W1^T into smem ----
    {
        const float4* node4 = (const float4*)node_emb;
        for (int i = tid; i < 2048; i += 256) {
            int k   = i >> 6;          // which triple (0..31)
            int j   = i & 63;          // float4 within 256-float node row
            int f   = j >> 4;          // factor
            int d4  = j & 15;          // float4 within 64-dim
            int row = k * 4 + f;
            float4 hv = node4[(size_t)s_idx[k]      * 64 + j];
            float4 tv = node4[(size_t)s_idx[32 + k] * 64 + j];
            *(float4*)&s_x[row * PITCH +      d4 * 4] = hv;
            *(float4*)&s_x[row * PITCH + 64 + d4 * 4] = tv;
        }
        for (int i = tid; i < 8192; i += 256) {
            int kk  = i >> 6;
            int col = i & 63;
            s_w1t[col * PITCH + kk] = W1[i];
        }
    }
    __syncthreads();

    // ---- Phase 2: register-tiled GEMM  C[128][64] = s_x[128][128] @ W1[128][64] ----
    const int ty = tid >> 3;   // 0..31 -> rows ty*4 + r
    const int tx = tid & 7;    // 0..7  -> cols tx + 8*c

    float acc[4][8];
    #pragma unroll
    for (int r = 0; r < 4; ++r)
        #pragma unroll
        for (int c = 0; c < 8; ++c) acc[r][c] = 0.f;

    #pragma unroll 2
    for (int q = 0; q < 32; ++q) {
        const int kk = q * 4;
        float4 a[4];
        #pragma unroll
        for (int r = 0; r < 4; ++r)
            a[r] = *(const float4*)&s_x[(ty * 4 + r) * PITCH + kk];
        float4 bb[8];
        #pragma unroll
        for (int c = 0; c < 8; ++c)
            bb[c] = *(const float4*)&s_w1t[(tx + c * 8) * PITCH + kk];
        #pragma unroll
        for (int r = 0; r < 4; ++r) {
            #pragma unroll
            for (int c = 0; c < 8; ++c) {
                acc[r][c] = fmaf(a[r].x, bb[c].x, acc[r][c]);
                acc[r][c] = fmaf(a[r].y, bb[c].y, acc[r][c]);
                acc[r][c] = fmaf(a[r].z, bb[c].z, acc[r][c]);
                acc[r][c] = fmaf(a[r].w, bb[c].w, acc[r][c]);
            }
        }
    }

    // ---- Phase 3: bias + relu + dot(W2) -> logits (shuffle-reduce over tx) ----
    {
        const float b2v = b2[0];
        float b1c[8], w2c[8];
        #pragma unroll
        for (int c = 0; c < 8; ++c) {
            b1c[c] = s_b1[tx + c * 8];
            w2c[c] = s_w2[tx + c * 8];
        }
        #pragma unroll
        for (int r = 0; r < 4; ++r) {
            float p = 0.f;
            #pragma unroll
            for (int c = 0; c < 8; ++c)
                p += fmaxf(acc[r][c] + b1c[c], 0.f) * w2c[c];
            p += __shfl_xor_sync(0xffffffffu, p, 1);
            p += __shfl_xor_sync(0xffffffffu, p, 2);
            p += __shfl_xor_sync(0xffffffffu, p, 4);
            if (tx == 0) s_logit[ty * 4 + r] = p + b2v;
        }
    }
    __syncthreads();

    // ---- Phase 4: softmax over k (per factor f). row = k*4+f ----
    if (tid < 128) {
        int f = tid >> 5, k = tid & 31;   // warp f, lane k
        float x = s_logit[k * 4 + f];
        float m = x;
        #pragma unroll
        for (int o = 16; o; o >>= 1)
            m = fmaxf(m, __shfl_xor_sync(0xffffffffu, m, o));
        float e = __expf(x - m);
        float s = e;
        #pragma unroll
        for (int o = 16; o; o >>= 1)
            s += __shfl_xor_sync(0xffffffffu, s, o);
        s_w[k * 4 + f] = e / s;
    }
    __syncthreads();

    // ---- Phase 5: weighted sum of t over k; write layer output ----
    {
        int f = tid >> 6;      // 0..3
        int d = tid & 63;      // 0..63
        float sum = 0.f;
        #pragma unroll 4
        for (int k = 0; k < 32; ++k)
            sum += s_w[k * 4 + f] * s_x[(k * 4 + f) * PITCH + 64 + d];
        // out[tower][1+layer][b][f][d]
        out[(((size_t)tower * 3 + 1 + layer) * 1024 + b) * 256 + f * 64 + d] = sum;
    }
}

extern "C" void kernel_launch(void* const* d_in, const int* in_sizes, int n_in,
                              void* d_out, int out_size)
{
    const float* node_emb = (const float*)d_in[0];
    // d_in[1] = relation_emb: unused by the reference computation
    const float* W1    = (const float*)d_in[2];
    const float* b1    = (const float*)d_in[3];
    const float* W2    = (const float*)d_in[4];
    const float* b2    = (const float*)d_in[5];
    const int*   users = (const int*)d_in[6];
    const int*   items = (const int*)d_in[7];
    const int*   utri  = (const int*)d_in[8];
    const int*   itri  = (const int*)d_in[9];
    float*       out   = (float*)d_out;

    const int smem_bytes = SMEM_FLOATS * 4;   // ~103 KB
    cudaFuncSetAttribute(kgat_fused_kernel,
                         cudaFuncAttributeMaxDynamicSharedMemorySize, smem_bytes);

    kgat_fused_kernel<<<4096, 256, smem_bytes>>>(
        node_emb, W1, b1, W2, b2, users, items, utri, itri, out);
}

// round 4
// speedup vs baseline: 3.5521x; 3.5521x over previous
#include <cuda_runtime.h>
#include <cuda_bf16.h>
#include <cstdint>

// smem byte layout
#define S_W1   0          // 16KB: W1 bf16 [k=128][n=64], 16B-slot XOR swizzle
#define S_X    16384      // 8 warps x 8KB: X bf16 [32 rows][128 k] (h|t), swizzled
#define S_T    81920      // 8 warps x 8KB: t fp32 [32 rows][64], float4-slot swizzle
#define S_WGT  147456     // 8 warps x 32 floats
#define SMEM_BYTES 148480

#define N_UNITS 16384     // 4096 tiles * 4 factors

static __device__ __forceinline__ uint32_t smem_u32(const void* p) {
    uint32_t a;
    asm("{ .reg .u64 t; cvta.to.shared.u64 t, %1; cvt.u32.u64 %0, t; }" : "=r"(a) : "l"(p));
    return a;
}
// returns {lo, hi} packed bf16x2
static __device__ __forceinline__ uint32_t pack2(float lo, float hi) {
    uint32_t r;
    asm("cvt.rn.bf16x2.f32 %0, %1, %2;" : "=r"(r) : "f"(hi), "f"(lo));
    return r;
}

#define LDSM_X4(a0,a1,a2,a3,addr) \
    asm volatile("ldmatrix.sync.aligned.m8n8.x4.shared.b16 {%0,%1,%2,%3}, [%4];" \
        : "=r"(a0),"=r"(a1),"=r"(a2),"=r"(a3) : "r"(addr))
#define LDSM_X2T(b0,b1,addr) \
    asm volatile("ldmatrix.sync.aligned.m8n8.x2.trans.shared.b16 {%0,%1}, [%2];" \
        : "=r"(b0),"=r"(b1) : "r"(addr))
#define MMA16816(d,a0,a1,a2,a3,b0,b1) \
    asm volatile("mma.sync.aligned.m16n8k16.row.col.f32.bf16.bf16.f32 " \
        "{%0,%1,%2,%3}, {%4,%5,%6,%7}, {%8,%9}, {%0,%1,%2,%3};" \
        : "+f"((d)[0]),"+f"((d)[1]),"+f"((d)[2]),"+f"((d)[3]) \
        : "r"(a0),"r"(a1),"r"(a2),"r"(a3),"r"(b0),"r"(b1))

__global__ __launch_bounds__(256, 1)
void kgat_hmma_kernel(const float* __restrict__ node_emb,
                      const float* __restrict__ W1,
                      const float* __restrict__ b1,
                      const float* __restrict__ W2,
                      const float* __restrict__ b2,
                      const int*   __restrict__ users,
                      const int*   __restrict__ items,
                      const int*   __restrict__ utri,
                      const int*   __restrict__ itri,
                      float*       __restrict__ out)
{
    extern __shared__ char smem[];
    const int tid  = threadIdx.x;
    const int wid  = tid >> 5;
    const int lane = tid & 31;
    const int g    = lane >> 2;     // 0..7
    const int tc   = lane & 3;      // 0..3

    // ---- one-time: W1 -> bf16 smem [kk][n], slot swizzle s' = (n>>3)^(kk&7) ----
    for (int i = tid; i < 8192; i += 256) {
        int kk = i >> 6, n = i & 63;
        uint32_t byte = (uint32_t)kk * 128u + ((((uint32_t)n >> 3) ^ ((uint32_t)kk & 7)) << 4)
                        + (((uint32_t)n & 7) << 1);
        *(__nv_bfloat16*)(smem + S_W1 + byte) = __float2bfloat16(W1[i]);
    }
    __syncthreads();

    const uint32_t sb   = smem_u32(smem);
    const uint32_t Xu   = sb + S_X + (uint32_t)wid * 8192u;  // this warp's X tile
    const uint32_t Wu   = sb + S_W1;
    char*   Xc   = smem + S_X + wid * 8192;
    float*  stw  = (float*)(smem + S_T + wid * 8192);
    float4* stw4 = (float4*)stw;
    float*  swgt = (float*)(smem + S_WGT) + wid * 32;
    const float4* node4 = (const float4*)node_emb;

    // ---- resident per-thread epilogue params ----
    float rb1[8][2], rw2[8][2];
    #pragma unroll
    for (int nt = 0; nt < 8; ++nt) {
        int n0 = nt * 8 + tc * 2;
        rb1[nt][0] = b1[n0];     rb1[nt][1] = b1[n0 + 1];
        rw2[nt][0] = W2[n0];     rw2[nt][1] = W2[n0 + 1];
    }
    const float b2v = b2[0];

    const int nstream = gridDim.x * 8;
    for (int u = blockIdx.x * 8 + wid; u < N_UNITS; u += nstream) {
        const int tile  = u >> 2;
        const int f     = u & 3;
        const int tower = tile >> 11;
        const int b     = (tile >> 1) & 1023;
        const int layer = tile & 1;
        const int* tri  = tower ? itri : utri;

        // lane k's indices
        const int hidx = tri[((b * 3 + 0) * 2 + layer) * 32 + lane];
        const int tidx = tri[((b * 3 + 2) * 2 + layer) * 32 + lane];

        // ---- gather: 32 h rows + 32 t rows (256B each) ----
        // iter i: rows r = 2i + (lane>>4), float4 chunk c = lane&15
        #pragma unroll
        for (int i = 0; i < 16; ++i) {
            const int r = 2 * i + (lane >> 4);
            const int c = lane & 15;
            const int hi = __shfl_sync(0xffffffffu, hidx, r);
            const int ti = __shfl_sync(0xffffffffu, tidx, r);
            float4 hv = node4[((size_t)hi * 4 + f) * 16 + c];
            float4 tv = node4[((size_t)ti * 4 + f) * 16 + c];
            // X row r: h at bf16 cols 4c.. (slot c>>1), t at cols 64+4c (slot 8+(c>>1))
            uint2 hp; hp.x = pack2(hv.x, hv.y); hp.y = pack2(hv.z, hv.w);
            uint2 tp; tp.x = pack2(tv.x, tv.y); tp.y = pack2(tv.z, tv.w);
            const uint32_t half = ((uint32_t)c & 1) << 3;
            *(uint2*)(Xc + r * 256 + ((((c >> 1)    ) ^ (r & 7)) << 4) + half) = hp;
            *(uint2*)(Xc + r * 256 + ((((c >> 1) + 8) ^ (r & 7)) << 4) + half) = tp;
            // fp32 t tile, float4-slot swizzle
            stw4[r * 16 + (c ^ (r & 15))] = tv;
        }

        // ---- origin slice (exact copy), one warp per (tile layer0, f) ----
        if (layer == 0) {
            const int oidx = (tower ? items : users)[b];
            float* outp = out + ((size_t)(tower * 3) * 1024 + b) * 256 + f * 64;
            ((float2*)outp)[lane] =
                ((const float2*)(node_emb + ((size_t)oidx * 4 + f) * 64))[lane];
        }
        __syncwarp();

        // ---- GEMM: C[32][64] = X[32][128] @ W1[128][64], bf16 HMMA ----
        float acc[2][8][4];
        #pragma unroll
        for (int mt = 0; mt < 2; ++mt)
            #pragma unroll
            for (int nt = 0; nt < 8; ++nt)
                #pragma unroll
                for (int e = 0; e < 4; ++e) acc[mt][nt][e] = 0.f;

        #pragma unroll
        for (int ks = 0; ks < 8; ++ks) {
            // B fragments: 8 n-tiles, k rows 16ks..16ks+15
            uint32_t B0[8], B1[8];
            const int krow = ks * 16 + (lane & 15);
            #pragma unroll
            for (int nt = 0; nt < 8; ++nt) {
                const uint32_t baddr = Wu + (uint32_t)krow * 128u
                                       + ((((uint32_t)nt) ^ ((uint32_t)krow & 7)) << 4);
                LDSM_X2T(B0[nt], B1[nt], baddr);
            }
            #pragma unroll
            for (int mt = 0; mt < 2; ++mt) {
                const int r = mt * 16 + (lane & 15);
                const uint32_t slot = (uint32_t)(2 * ks + (lane >> 4));
                const uint32_t aaddr = Xu + (uint32_t)r * 256u + ((slot ^ ((uint32_t)r & 7)) << 4);
                uint32_t a0, a1, a2, a3;
                LDSM_X4(a0, a1, a2, a3, aaddr);
                #pragma unroll
                for (int nt = 0; nt < 8; ++nt)
                    MMA16816(acc[mt][nt], a0, a1, a2, a3, B0[nt], B1[nt]);
            }
        }

        // ---- logits: relu(C + b1) . W2 + b2 ; rows g,g+8 per m-tile ----
        float lg[4];
        #pragma unroll
        for (int mt = 0; mt < 2; ++mt) {
            float p0 = 0.f, p1 = 0.f;
            #pragma unroll
            for (int nt = 0; nt < 8; ++nt) {
                p0 += fmaxf(acc[mt][nt][0] + rb1[nt][0], 0.f) * rw2[nt][0]
                    + fmaxf(acc[mt][nt][1] + rb1[nt][1], 0.f) * rw2[nt][1];
                p1 += fmaxf(acc[mt][nt][2] + rb1[nt][0], 0.f) * rw2[nt][0]
                    + fmaxf(acc[mt][nt][3] + rb1[nt][1], 0.f) * rw2[nt][1];
            }
            p0 += __shfl_xor_sync(0xffffffffu, p0, 1);
            p0 += __shfl_xor_sync(0xffffffffu, p0, 2);
            p1 += __shfl_xor_sync(0xffffffffu, p1, 1);
            p1 += __shfl_xor_sync(0xffffffffu, p1, 2);
            lg[mt * 2]     = p0 + b2v;   // row mt*16 + g
            lg[mt * 2 + 1] = p1 + b2v;   // row mt*16 + g + 8
        }

        // ---- softmax over the warp's 32 rows ----
        // lane holds rows {g, g+8, 16+g, 24+g}; tc-groups are duplicates
        float m = fmaxf(fmaxf(lg[0], lg[1]), fmaxf(lg[2], lg[3]));
        #pragma unroll
        for (int o = 4; o <= 16; o <<= 1)
            m = fmaxf(m, __shfl_xor_sync(0xffffffffu, m, o));
        float e0 = __expf(lg[0] - m), e1 = __expf(lg[1] - m);
        float e2 = __expf(lg[2] - m), e3 = __expf(lg[3] - m);
        float s = e0 + e1 + e2 + e3;
        #pragma unroll
        for (int o = 4; o <= 16; o <<= 1)
            s += __shfl_xor_sync(0xffffffffu, s, o);
        const float rs = __frcp_rn(s);
        if (tc == 0) {
            swgt[g]      = e0 * rs;
            swgt[g + 8]  = e1 * rs;
            swgt[g + 16] = e2 * rs;
            swgt[g + 24] = e3 * rs;
        }
        __syncwarp();

        // ---- weighted sum of fp32 t over k; d0 = lane, d1 = lane+32 ----
        {
            float a0 = 0.f, a1 = 0.f;
            #pragma unroll
            for (int rr = 0; rr < 32; ++rr) {
                const float w = swgt[rr];
                const int slot = (lane >> 2) ^ (rr & 15);
                a0 += w * stw[rr * 64 + ((slot    ) << 2) + (lane & 3)];
                a1 += w * stw[rr * 64 + ((slot ^ 8) << 2) + (lane & 3)];
            }
            float* outp = out + (((size_t)(tower * 3 + 1 + layer)) * 1024 + b) * 256 + f * 64;
            outp[lane]      = a0;
            outp[lane + 32] = a1;
        }
        __syncwarp();   // protect X/stw/swgt before next unit's writes
    }
}

extern "C" void kernel_launch(void* const* d_in, const int* in_sizes, int n_in,
                              void* d_out, int out_size)
{
    const float* node_emb = (const float*)d_in[0];
    // d_in[1] = relation_emb: unused by the reference computation
    const float* W1    = (const float*)d_in[2];
    const float* b1    = (const float*)d_in[3];
    const float* W2    = (const float*)d_in[4];
    const float* b2    = (const float*)d_in[5];
    const int*   users = (const int*)d_in[6];
    const int*   items = (const int*)d_in[7];
    const int*   utri  = (const int*)d_in[8];
    const int*   itri  = (const int*)d_in[9];
    float*       out   = (float*)d_out;

    int nsm = 148;
    cudaDeviceGetAttribute(&nsm, cudaDevAttrMultiProcessorCount, 0);

    cudaFuncSetAttribute(kgat_hmma_kernel,
                         cudaFuncAttributeMaxDynamicSharedMemorySize, SMEM_BYTES);
    kgat_hmma_kernel<<<nsm, 256, SMEM_BYTES>>>(
        node_emb, W1, b1, W2, b2, users, items, utri, itri, out);
}

// round 7
// speedup vs baseline: 4.0612x; 1.1433x over previous
#include <cuda_runtime.h>
#include <cuda_bf16.h>
#include <cstdint>

// smem byte layout
#define S_W1   0          // 16KB: W1 bf16 [k=128][n=64], 16B-slot XOR swizzle
#define S_X    16384      // 8 warps x 8KB: X bf16 [32 rows][128 k] (h|t), swizzled
#define S_T    81920      // 8 warps x 8KB: t fp32 [32 rows][64], float4-slot swizzle
#define S_H    147456     // 8 warps x 8KB: h fp32 staging [32 rows][16 float4], linear
#define S_WGT  212992     // 8 warps x 32 floats
#define SMEM_BYTES 214016

#define N_UNITS 16384     // 4096 tiles * 4 factors

static __device__ __forceinline__ uint32_t smem_u32(const void* p) {
    uint32_t a;
    asm("{ .reg .u64 t; cvta.to.shared.u64 t, %1; cvt.u32.u64 %0, t; }" : "=r"(a) : "l"(p));
    return a;
}
// returns {lo, hi} packed bf16x2
static __device__ __forceinline__ uint32_t pack2(float lo, float hi) {
    uint32_t r;
    asm("cvt.rn.bf16x2.f32 %0, %1, %2;" : "=r"(r) : "f"(hi), "f"(lo));
    return r;
}
static __device__ __forceinline__ void cp_async16(uint32_t dst, const void* src) {
    asm volatile("cp.async.cg.shared.global [%0], [%1], 16;" :: "r"(dst), "l"(src) : "memory");
}

#define LDSM_X4(a0,a1,a2,a3,addr) \
    asm volatile("ldmatrix.sync.aligned.m8n8.x4.shared.b16 {%0,%1,%2,%3}, [%4];" \
        : "=r"(a0),"=r"(a1),"=r"(a2),"=r"(a3) : "r"(addr))
#define LDSM_X2T(b0,b1,addr) \
    asm volatile("ldmatrix.sync.aligned.m8n8.x2.trans.shared.b16 {%0,%1}, [%2];" \
        : "=r"(b0),"=r"(b1) : "r"(addr))
#define MMA16816(d,a0,a1,a2,a3,b0,b1) \
    asm volatile("mma.sync.aligned.m16n8k16.row.col.f32.bf16.bf16.f32 " \
        "{%0,%1,%2,%3}, {%4,%5,%6,%7}, {%8,%9}, {%0,%1,%2,%3};" \
        : "+f"((d)[0]),"+f"((d)[1]),"+f"((d)[2]),"+f"((d)[3]) \
        : "r"(a0),"r"(a1),"r"(a2),"r"(a3),"r"(b0),"r"(b1))

__global__ __launch_bounds__(256, 1)
void kgat_hmma_kernel(const float* __restrict__ node_emb,
                      const float* __restrict__ W1,
                      const float* __restrict__ b1,
                      const float* __restrict__ W2,
                      const float* __restrict__ b2,
                      const int*   __restrict__ users,
                      const int*   __restrict__ items,
                      const int*   __restrict__ utri,
                      const int*   __restrict__ itri,
                      float*       __restrict__ out)
{
    extern __shared__ char smem[];
    const int tid  = threadIdx.x;
    const int wid  = tid >> 5;
    const int lane = tid & 31;
    const int g    = lane >> 2;     // 0..7
    const int tc   = lane & 3;      // 0..3

    // ---- one-time: W1 -> bf16 smem [kk][n], slot swizzle s' = (n>>3)^(kk&7) ----
    for (int i = tid; i < 8192; i += 256) {
        int kk = i >> 6, n = i & 63;
        uint32_t byte = (uint32_t)kk * 128u + ((((uint32_t)n >> 3) ^ ((uint32_t)kk & 7)) << 4)
                        + (((uint32_t)n & 7) << 1);
        *(__nv_bfloat16*)(smem + S_W1 + byte) = __float2bfloat16(W1[i]);
    }
    __syncthreads();

    const uint32_t sb   = smem_u32(smem);
    const uint32_t Xu   = sb + S_X + (uint32_t)wid * 8192u;  // this warp's X tile
    const uint32_t Tu   = sb + S_T + (uint32_t)wid * 8192u;
    const uint32_t Hu   = sb + S_H + (uint32_t)wid * 8192u;
    const uint32_t Wu   = sb + S_W1;
    char*   Xc   = smem + S_X + wid * 8192;
    float*  stw  = (float*)(smem + S_T + wid * 8192);
    float4* stw4 = (float4*)stw;
    float4* Hf4  = (float4*)(smem + S_H + wid * 8192);
    float*  swgt = (float*)(smem + S_WGT) + wid * 32;
    const float* node_f = node_emb;

    // ---- resident per-thread epilogue params ----
    float rb1[8][2], rw2[8][2];
    #pragma unroll
    for (int nt = 0; nt < 8; ++nt) {
        int n0 = nt * 8 + tc * 2;
        rb1[nt][0] = b1[n0];     rb1[nt][1] = b1[n0 + 1];
        rw2[nt][0] = W2[n0];     rw2[nt][1] = W2[n0 + 1];
    }
    const float b2v = b2[0];

    const int nstream = gridDim.x * 8;
    for (int u = blockIdx.x * 8 + wid; u < N_UNITS; u += nstream) {
        const int tile  = u >> 2;
        const int f     = u & 3;
        const int tower = tile >> 11;
        const int b     = (tile >> 1) & 1023;
        const int layer = tile & 1;
        const int* tri  = tower ? itri : utri;

        // lane k's indices
        const int hidx = tri[((b * 3 + 0) * 2 + layer) * 32 + lane];
        const int tidx = tri[((b * 3 + 2) * 2 + layer) * 32 + lane];

        // ---- gather burst: 32 h rows + 32 t rows (256B each) via cp.async ----
        // iter i: rows r = 2i + (lane>>4), float4 chunk c = lane&15
        #pragma unroll
        for (int i = 0; i < 16; ++i) {
            const int r = 2 * i + (lane >> 4);
            const int c = lane & 15;
            const int hi = __shfl_sync(0xffffffffu, hidx, r);
            const int ti = __shfl_sync(0xffffffffu, tidx, r);
            const float* hsrc = node_f + (((size_t)hi * 4 + f) << 6) + (c << 2);
            const float* tsrc = node_f + (((size_t)ti * 4 + f) << 6) + (c << 2);
            cp_async16(Hu + (uint32_t)((r * 16 + c) << 4), hsrc);
            cp_async16(Tu + (uint32_t)((r * 16 + (c ^ (r & 15))) << 4), tsrc);
        }
        asm volatile("cp.async.commit_group;" ::: "memory");

        // ---- origin slice (exact copy), overlaps with the gather burst ----
        if (layer == 0) {
            const int oidx = (tower ? items : users)[b];
            float* outp = out + ((size_t)(tower * 3) * 1024 + b) * 256 + f * 64;
            ((float2*)outp)[lane] =
                ((const float2*)(node_emb + ((size_t)oidx * 4 + f) * 64))[lane];
        }

        asm volatile("cp.async.wait_group 0;" ::: "memory");
        __syncwarp();

        // ---- convert staging fp32 -> bf16 X tile (smem -> smem) ----
        #pragma unroll
        for (int i = 0; i < 16; ++i) {
            const int r = 2 * i + (lane >> 4);
            const int c = lane & 15;
            float4 hv = Hf4[r * 16 + c];
            float4 tv = stw4[r * 16 + (c ^ (r & 15))];
            uint2 hp; hp.x = pack2(hv.x, hv.y); hp.y = pack2(hv.z, hv.w);
            uint2 tp; tp.x = pack2(tv.x, tv.y); tp.y = pack2(tv.z, tv.w);
            const uint32_t half = ((uint32_t)c & 1) << 3;
            *(uint2*)(Xc + r * 256 + ((((c >> 1)    ) ^ (r & 7)) << 4) + half) = hp;
            *(uint2*)(Xc + r * 256 + ((((c >> 1) + 8) ^ (r & 7)) << 4) + half) = tp;
        }
        __syncwarp();

        // ---- GEMM: C[32][64] = X[32][128] @ W1[128][64], bf16 HMMA ----
        float acc[2][8][4];
        #pragma unroll
        for (int mt = 0; mt < 2; ++mt)
            #pragma unroll
            for (int nt = 0; nt < 8; ++nt)
                #pragma unroll
                for (int e = 0; e < 4; ++e) acc[mt][nt][e] = 0.f;

        #pragma unroll
        for (int ks = 0; ks < 8; ++ks) {
            uint32_t B0[8], B1[8];
            const int krow = ks * 16 + (lane & 15);
            #pragma unroll
            for (int nt = 0; nt < 8; ++nt) {
                const uint32_t baddr = Wu + (uint32_t)krow * 128u
                                       + ((((uint32_t)nt) ^ ((uint32_t)krow & 7)) << 4);
                LDSM_X2T(B0[nt], B1[nt], baddr);
            }
            #pragma unroll
            for (int mt = 0; mt < 2; ++mt) {
                const int r = mt * 16 + (lane & 15);
                const uint32_t slot = (uint32_t)(2 * ks + (lane >> 4));
                const uint32_t aaddr = Xu + (uint32_t)r * 256u + ((slot ^ ((uint32_t)r & 7)) << 4);
                uint32_t a0, a1, a2, a3;
                LDSM_X4(a0, a1, a2, a3, aaddr);
                #pragma unroll
                for (int nt = 0; nt < 8; ++nt)
                    MMA16816(acc[mt][nt], a0, a1, a2, a3, B0[nt], B1[nt]);
            }
        }

        // ---- logits: relu(C + b1) . W2 + b2 ; rows g,g+8 per m-tile ----
        float lg[4];
        #pragma unroll
        for (int mt = 0; mt < 2; ++mt) {
            float p0 = 0.f, p1 = 0.f;
            #pragma unroll
            for (int nt = 0; nt < 8; ++nt) {
                p0 += fmaxf(acc[mt][nt][0] + rb1[nt][0], 0.f) * rw2[nt][0]
                    + fmaxf(acc[mt][nt][1] + rb1[nt][1], 0.f) * rw2[nt][1];
                p1 += fmaxf(acc[mt][nt][2] + rb1[nt][0], 0.f) * rw2[nt][0]
                    + fmaxf(acc[mt][nt][3] + rb1[nt][1], 0.f) * rw2[nt][1];
            }
            p0 += __shfl_xor_sync(0xffffffffu, p0, 1);
            p0 += __shfl_xor_sync(0xffffffffu, p0, 2);
            p1 += __shfl_xor_sync(0xffffffffu, p1, 1);
            p1 += __shfl_xor_sync(0xffffffffu, p1, 2);
            lg[mt * 2]     = p0 + b2v;   // row mt*16 + g
            lg[mt * 2 + 1] = p1 + b2v;   // row mt*16 + g + 8
        }

        // ---- softmax over the warp's 32 rows ----
        float m = fmaxf(fmaxf(lg[0], lg[1]), fmaxf(lg[2], lg[3]));
        #pragma unroll
        for (int o = 4; o <= 16; o <<= 1)
            m = fmaxf(m, __shfl_xor_sync(0xffffffffu, m, o));
        float e0 = __expf(lg[0] - m), e1 = __expf(lg[1] - m);
        float e2 = __expf(lg[2] - m), e3 = __expf(lg[3] - m);
        float s = e0 + e1 + e2 + e3;
        #pragma unroll
        for (int o = 4; o <= 16; o <<= 1)
            s += __shfl_xor_sync(0xffffffffu, s, o);
        const float rs = __frcp_rn(s);
        if (tc == 0) {
            swgt[g]      = e0 * rs;
            swgt[g + 8]  = e1 * rs;
            swgt[g + 16] = e2 * rs;
            swgt[g + 24] = e3 * rs;
        }
        __syncwarp();

        // ---- weighted sum of fp32 t over k; d0 = lane, d1 = lane+32 ----
        {
            float a0 = 0.f, a1 = 0.f;
            #pragma unroll
            for (int rr = 0; rr < 32; ++rr) {
                const float w = swgt[rr];
                const int slot = (lane >> 2) ^ (rr & 15);
                a0 += w * stw[rr * 64 + ((slot    ) << 2) + (lane & 3)];
                a1 += w * stw[rr * 64 + ((slot ^ 8) << 2) + (lane & 3)];
            }
            float* outp = out + (((size_t)(tower * 3 + 1 + layer)) * 1024 + b) * 256 + f * 64;
            outp[lane]      = a0;
            outp[lane + 32] = a1;
        }
        __syncwarp();   // protect X/T/H/swgt before next unit's writes
    }
}

extern "C" void kernel_launch(void* const* d_in, const int* in_sizes, int n_in,
                              void* d_out, int out_size)
{
    const float* node_emb = (const float*)d_in[0];
    // d_in[1] = relation_emb: unused by the reference computation
    const float* W1    = (const float*)d_in[2];
    const float* b1    = (const float*)d_in[3];
    const float* W2    = (const float*)d_in[4];
    const float* b2    = (const float*)d_in[5];
    const int*   users = (const int*)d_in[6];
    const int*   items = (const int*)d_in[7];
    const int*   utri  = (const int*)d_in[8];
    const int*   itri  = (const int*)d_in[9];
    float*       out   = (float*)d_out;

    int nsm = 148;
    cudaDeviceGetAttribute(&nsm, cudaDevAttrMultiProcessorCount, 0);

    cudaFuncSetAttribute(kgat_hmma_kernel,
                         cudaFuncAttributeMaxDynamicSharedMemorySize, SMEM_BYTES);
    kgat_hmma_kernel<<<nsm, 256, SMEM_BYTES>>>(
        node_emb, W1, b1, W2, b2, users, items, utri, itri, out);
}